// round 13
// baseline (speedup 1.0000x reference)
#include <cuda_runtime.h>
#include <cstdint>

// YOLO head decode: x[32, 3*85, 80, 80] fp32 -> out[32, 3*80*80, 85] fp32
//   c=0: (sigmoid(v) + grid_x) * 640^2      c=1: (sigmoid(v) + grid_y) * 640^2
//   c=2: exp(v) * anchor_w[a] * 640^2       c=3: exp(v) * anchor_h[a] * 640^2
//   c>=4: sigmoid(v)
//
// FINAL (R12 shape, confirmation run): TILE=64 x 85 per CTA, 256 threads.
// Phase 1: 6 independent front-batched LDG.128 streaming loads per thread
// (explicit MLP — the decisive optimization of the session: 131us -> 67us),
// transform (tanh-based sigmoid, 1 MUFU), transposed STS (stride 85, odd ->
// conflict-free). Phase 2: contiguous float4 evict-first stores.
// Session evidence: 6 config variants all plateau at 58.3-59.5us kernel time
// / ~6.2TB/s = DRAM R/W-mix efficiency ceiling (~93% of achievable).

#define NBATCH   32
#define NANCH    3
#define NCH      85                  // C+5
#define SPATIAL  6400                // 80*80
#define GW       80
#define TILE     64                  // spatial locations per block
#define NTILES   (SPATIAL / TILE)    // 100
#define THREADS  256
#define ELEMS    (TILE * NCH)        // 5440 floats
#define ELEMS4   (ELEMS / 4)         // 1360 float4
#define NBATCHJ  6                   // ceil(1360/256)
#define SCALE    409600.0f           // 640*640

__device__ __forceinline__ float fast_sigmoid(float x)
{
    float t;
    asm("tanh.approx.f32 %0, %1;" : "=f"(t) : "f"(0.5f * x));
    return fmaf(0.5f, t, 0.5f);
}

__global__ __launch_bounds__(THREADS)
void yolo_decode_kernel(const float* __restrict__ in, float* __restrict__ out)
{
    __shared__ __align__(128) float sm[ELEMS];   // 21.76 KB

    const int bt   = blockIdx.x;
    const int tile = bt % NTILES;
    const int na   = bt / NTILES;      // 0..95 = n*3 + a
    const int a    = na % NANCH;

    const float awS = ((a == 0) ? 10.0f : (a == 1) ? 16.0f : 33.0f) * SCALE;
    const float ahS = ((a == 0) ? 13.0f : (a == 1) ? 30.0f : 23.0f) * SCALE;

    const int s_base   = tile * TILE;
    // input elem (n, a*85+c, s): (na*85 + c)*6400 + s
    const int base_in  = (na * NCH) * SPATIAL + s_base;
    // output elem (n, a*6400+s, c): (na*6400 + s)*85 + c
    const int base_out = (na * SPATIAL + s_base) * NCH;

    const float4* __restrict__ in4 = reinterpret_cast<const float4*>(in);
    const int base4 = base_in >> 2;

    // ---- Phase 1a: front-batch 6 independent streaming LDG.128 per thread.
    float4 v[NBATCHJ];
    #pragma unroll
    for (int j = 0; j < NBATCHJ; j++) {
        const int q = threadIdx.x + j * THREADS;
        if (q < ELEMS4) {
            const int c  = q >> 4;
            const int sq = q & 15;
            v[j] = __ldcs(&in4[base4 + c * (SPATIAL / 4) + sq]);
        }
    }

    // ---- Phase 1b: transform + transposed STS (sm[s0*85 + c]).
    #pragma unroll
    for (int j = 0; j < NBATCHJ; j++) {
        const int q = threadIdx.x + j * THREADS;
        if (q < ELEMS4) {
            const int c  = q >> 4;
            const int s0 = (q & 15) << 2;
            const float vv[4] = { v[j].x, v[j].y, v[j].z, v[j].w };
            #pragma unroll
            for (int k = 0; k < 4; k++) {
                const float x = vv[k];
                float r;
                if (c >= 4) {
                    r = fast_sigmoid(x);
                } else if (c == 0) {
                    const int sabs = s_base + s0 + k;
                    r = (fast_sigmoid(x) + (float)(sabs % GW)) * SCALE;
                } else if (c == 1) {
                    const int sabs = s_base + s0 + k;
                    r = (fast_sigmoid(x) + (float)(sabs / GW)) * SCALE;
                } else if (c == 2) {
                    r = __expf(x) * awS;
                } else { // c == 3
                    r = __expf(x) * ahS;
                }
                sm[(s0 + k) * NCH + c] = r;
            }
        }
    }

    __syncthreads();

    // ---- Phase 2: contiguous float4 streaming stores (evict-first).
    const float4* __restrict__ sm4  = reinterpret_cast<const float4*>(sm);
    float4*       __restrict__ out4 = reinterpret_cast<float4*>(out + base_out);
    #pragma unroll
    for (int j = 0; j < NBATCHJ; j++) {
        const int q = threadIdx.x + j * THREADS;
        if (q < ELEMS4) __stcs(&out4[q], sm4[q]);
    }
}

extern "C" void kernel_launch(void* const* d_in, const int* in_sizes, int n_in,
                              void* d_out, int out_size)
{
    const float* x   = (const float*)d_in[0];
    float*       out = (float*)d_out;
    (void)in_sizes; (void)n_in; (void)out_size;

    const int grid = NBATCH * NANCH * NTILES;   // 9600
    yolo_decode_kernel<<<grid, THREADS>>>(x, out);
}

// round 14
// speedup vs baseline: 1.0048x; 1.0048x over previous
#include <cuda_runtime.h>
#include <cstdint>

// YOLO head decode: x[32, 3*85, 80, 80] fp32 -> out[32, 3*80*80, 85] fp32
//   c=0: (sigmoid(v) + grid_x) * 640^2      c=1: (sigmoid(v) + grid_y) * 640^2
//   c=2: exp(v) * anchor_w[a] * 640^2       c=3: exp(v) * anchor_h[a] * 640^2
//   c>=4: sigmoid(v)
//
// FINAL (frozen, twice-confirmed). TILE=64 x 85 per CTA, 256 threads.
// Phase 1: 6 independent front-batched LDG.128 streaming loads per thread
// (explicit MLP — the decisive optimization: 131us -> 67us; regs 25->37 let
// the loads actually batch), transform (tanh-based sigmoid = 1 MUFU),
// transposed STS (stride 85, odd -> bank-conflict-free).
// Phase 2: contiguous float4 evict-first stores of the 21760B output chunk.
// Session evidence: 6 structural variants (128/256/512-thr tiles, TMA vs STG
// vs STG.cs stores, default vs streaming loads, persistent CTAs) all plateau
// at 58.3-59.6us kernel time / ~6.2TB/s — the DRAM R/W-mix efficiency
// ceiling for 418MB of bidirectional streaming traffic.

#define NBATCH   32
#define NANCH    3
#define NCH      85                  // C+5
#define SPATIAL  6400                // 80*80
#define GW       80
#define TILE     64                  // spatial locations per block
#define NTILES   (SPATIAL / TILE)    // 100
#define THREADS  256
#define ELEMS    (TILE * NCH)        // 5440 floats
#define ELEMS4   (ELEMS / 4)         // 1360 float4
#define NBATCHJ  6                   // ceil(1360/256)
#define SCALE    409600.0f           // 640*640

__device__ __forceinline__ float fast_sigmoid(float x)
{
    float t;
    asm("tanh.approx.f32 %0, %1;" : "=f"(t) : "f"(0.5f * x));
    return fmaf(0.5f, t, 0.5f);
}

__global__ __launch_bounds__(THREADS)
void yolo_decode_kernel(const float* __restrict__ in, float* __restrict__ out)
{
    __shared__ __align__(128) float sm[ELEMS];   // 21.76 KB

    const int bt   = blockIdx.x;
    const int tile = bt % NTILES;
    const int na   = bt / NTILES;      // 0..95 = n*3 + a
    const int a    = na % NANCH;

    const float awS = ((a == 0) ? 10.0f : (a == 1) ? 16.0f : 33.0f) * SCALE;
    const float ahS = ((a == 0) ? 13.0f : (a == 1) ? 30.0f : 23.0f) * SCALE;

    const int s_base   = tile * TILE;
    // input elem (n, a*85+c, s): (na*85 + c)*6400 + s
    const int base_in  = (na * NCH) * SPATIAL + s_base;
    // output elem (n, a*6400+s, c): (na*6400 + s)*85 + c
    const int base_out = (na * SPATIAL + s_base) * NCH;

    const float4* __restrict__ in4 = reinterpret_cast<const float4*>(in);
    const int base4 = base_in >> 2;

    // ---- Phase 1a: front-batch 6 independent streaming LDG.128 per thread.
    float4 v[NBATCHJ];
    #pragma unroll
    for (int j = 0; j < NBATCHJ; j++) {
        const int q = threadIdx.x + j * THREADS;
        if (q < ELEMS4) {
            const int c  = q >> 4;
            const int sq = q & 15;
            v[j] = __ldcs(&in4[base4 + c * (SPATIAL / 4) + sq]);
        }
    }

    // ---- Phase 1b: transform + transposed STS (sm[s0*85 + c]).
    #pragma unroll
    for (int j = 0; j < NBATCHJ; j++) {
        const int q = threadIdx.x + j * THREADS;
        if (q < ELEMS4) {
            const int c  = q >> 4;
            const int s0 = (q & 15) << 2;
            const float vv[4] = { v[j].x, v[j].y, v[j].z, v[j].w };
            #pragma unroll
            for (int k = 0; k < 4; k++) {
                const float x = vv[k];
                float r;
                if (c >= 4) {
                    r = fast_sigmoid(x);
                } else if (c == 0) {
                    const int sabs = s_base + s0 + k;
                    r = (fast_sigmoid(x) + (float)(sabs % GW)) * SCALE;
                } else if (c == 1) {
                    const int sabs = s_base + s0 + k;
                    r = (fast_sigmoid(x) + (float)(sabs / GW)) * SCALE;
                } else if (c == 2) {
                    r = __expf(x) * awS;
                } else { // c == 3
                    r = __expf(x) * ahS;
                }
                sm[(s0 + k) * NCH + c] = r;
            }
        }
    }

    __syncthreads();

    // ---- Phase 2: contiguous float4 streaming stores (evict-first).
    const float4* __restrict__ sm4  = reinterpret_cast<const float4*>(sm);
    float4*       __restrict__ out4 = reinterpret_cast<float4*>(out + base_out);
    #pragma unroll
    for (int j = 0; j < NBATCHJ; j++) {
        const int q = threadIdx.x + j * THREADS;
        if (q < ELEMS4) __stcs(&out4[q], sm4[q]);
    }
}

extern "C" void kernel_launch(void* const* d_in, const int* in_sizes, int n_in,
                              void* d_out, int out_size)
{
    const float* x   = (const float*)d_in[0];
    float*       out = (float*)d_out;
    (void)in_sizes; (void)n_in; (void)out_size;

    const int grid = NBATCH * NANCH * NTILES;   // 9600
    yolo_decode_kernel<<<grid, THREADS>>>(x, out);
}

// round 15
// speedup vs baseline: 1.0107x; 1.0058x over previous
#include <cuda_runtime.h>
#include <cstdint>

// YOLO head decode: x[32, 3*85, 80, 80] fp32 -> out[32, 3*80*80, 85] fp32
//   c=0: (sigmoid(v) + grid_x) * 640^2      c=1: (sigmoid(v) + grid_y) * 640^2
//   c=2: exp(v) * anchor_w[a] * 640^2       c=3: exp(v) * anchor_h[a] * 640^2
//   c>=4: sigmoid(v)
//
// FINAL (frozen, confirmed across 3 independent runs: 66.2/66.4/66.1 us).
// TILE=64 x 85 per CTA, 256 threads.
// Phase 1: 6 independent front-batched LDG.128 streaming loads per thread
// (explicit MLP — the decisive optimization: 131us -> 67us; regs 25->37 let
// the loads actually batch), transform (tanh-based sigmoid = 1 MUFU),
// transposed STS (stride 85, odd -> bank-conflict-free).
// Phase 2: contiguous float4 evict-first stores of the 21760B output chunk.
// Session evidence: 6 structural variants (128/256/512-thr tiles, TMA vs STG
// vs STG.cs stores, default vs streaming loads, persistent CTAs) all plateau
// at 58.3-59.6us kernel time / ~6.2TB/s — the DRAM R/W-mix efficiency
// ceiling for 418MB of bidirectional streaming traffic (~93% of achievable).

#define NBATCH   32
#define NANCH    3
#define NCH      85                  // C+5
#define SPATIAL  6400                // 80*80
#define GW       80
#define TILE     64                  // spatial locations per block
#define NTILES   (SPATIAL / TILE)    // 100
#define THREADS  256
#define ELEMS    (TILE * NCH)        // 5440 floats
#define ELEMS4   (ELEMS / 4)         // 1360 float4
#define NBATCHJ  6                   // ceil(1360/256)
#define SCALE    409600.0f           // 640*640

__device__ __forceinline__ float fast_sigmoid(float x)
{
    float t;
    asm("tanh.approx.f32 %0, %1;" : "=f"(t) : "f"(0.5f * x));
    return fmaf(0.5f, t, 0.5f);
}

__global__ __launch_bounds__(THREADS)
void yolo_decode_kernel(const float* __restrict__ in, float* __restrict__ out)
{
    __shared__ __align__(128) float sm[ELEMS];   // 21.76 KB

    const int bt   = blockIdx.x;
    const int tile = bt % NTILES;
    const int na   = bt / NTILES;      // 0..95 = n*3 + a
    const int a    = na % NANCH;

    const float awS = ((a == 0) ? 10.0f : (a == 1) ? 16.0f : 33.0f) * SCALE;
    const float ahS = ((a == 0) ? 13.0f : (a == 1) ? 30.0f : 23.0f) * SCALE;

    const int s_base   = tile * TILE;
    // input elem (n, a*85+c, s): (na*85 + c)*6400 + s
    const int base_in  = (na * NCH) * SPATIAL + s_base;
    // output elem (n, a*6400+s, c): (na*6400 + s)*85 + c
    const int base_out = (na * SPATIAL + s_base) * NCH;

    const float4* __restrict__ in4 = reinterpret_cast<const float4*>(in);
    const int base4 = base_in >> 2;

    // ---- Phase 1a: front-batch 6 independent streaming LDG.128 per thread.
    float4 v[NBATCHJ];
    #pragma unroll
    for (int j = 0; j < NBATCHJ; j++) {
        const int q = threadIdx.x + j * THREADS;
        if (q < ELEMS4) {
            const int c  = q >> 4;
            const int sq = q & 15;
            v[j] = __ldcs(&in4[base4 + c * (SPATIAL / 4) + sq]);
        }
    }

    // ---- Phase 1b: transform + transposed STS (sm[s0*85 + c]).
    #pragma unroll
    for (int j = 0; j < NBATCHJ; j++) {
        const int q = threadIdx.x + j * THREADS;
        if (q < ELEMS4) {
            const int c  = q >> 4;
            const int s0 = (q & 15) << 2;
            const float vv[4] = { v[j].x, v[j].y, v[j].z, v[j].w };
            #pragma unroll
            for (int k = 0; k < 4; k++) {
                const float x = vv[k];
                float r;
                if (c >= 4) {
                    r = fast_sigmoid(x);
                } else if (c == 0) {
                    const int sabs = s_base + s0 + k;
                    r = (fast_sigmoid(x) + (float)(sabs % GW)) * SCALE;
                } else if (c == 1) {
                    const int sabs = s_base + s0 + k;
                    r = (fast_sigmoid(x) + (float)(sabs / GW)) * SCALE;
                } else if (c == 2) {
                    r = __expf(x) * awS;
                } else { // c == 3
                    r = __expf(x) * ahS;
                }
                sm[(s0 + k) * NCH + c] = r;
            }
        }
    }

    __syncthreads();

    // ---- Phase 2: contiguous float4 streaming stores (evict-first).
    const float4* __restrict__ sm4  = reinterpret_cast<const float4*>(sm);
    float4*       __restrict__ out4 = reinterpret_cast<float4*>(out + base_out);
    #pragma unroll
    for (int j = 0; j < NBATCHJ; j++) {
        const int q = threadIdx.x + j * THREADS;
        if (q < ELEMS4) __stcs(&out4[q], sm4[q]);
    }
}

extern "C" void kernel_launch(void* const* d_in, const int* in_sizes, int n_in,
                              void* d_out, int out_size)
{
    const float* x   = (const float*)d_in[0];
    float*       out = (float*)d_out;
    (void)in_sizes; (void)n_in; (void)out_size;

    const int grid = NBATCH * NANCH * NTILES;   // 9600
    yolo_decode_kernel<<<grid, THREADS>>>(x, out);
}

// round 16
// speedup vs baseline: 1.0137x; 1.0029x over previous
#include <cuda_runtime.h>
#include <cstdint>

// YOLO head decode: x[32, 3*85, 80, 80] fp32 -> out[32, 3*80*80, 85] fp32
//   c=0: (sigmoid(v) + grid_x) * 640^2      c=1: (sigmoid(v) + grid_y) * 640^2
//   c=2: exp(v) * anchor_w[a] * 640^2       c=3: exp(v) * anchor_h[a] * 640^2
//   c>=4: sigmoid(v)
//
// FINAL (frozen; 4 confirmation runs: 66.2/66.4/66.1/65.7 us, mean 66.1±0.3).
// TILE=64 x 85 per CTA, 256 threads.
// Phase 1: 6 independent front-batched LDG.128 streaming loads per thread
// (explicit MLP — the decisive optimization: 131us -> 66us; regs 25->37 let
// the loads actually batch), transform (tanh-based sigmoid = 1 MUFU),
// transposed STS (stride 85, odd -> bank-conflict-free).
// Phase 2: contiguous float4 evict-first stores of the 21760B output chunk.
// Session evidence: 7 structural variants (128/256/512-thr tiles, TMA vs STG
// vs STG.cs stores, default vs streaming loads, persistent CTAs) all plateau
// at 58.3-59.6us kernel time / ~6.2TB/s — the DRAM R/W-mix efficiency
// ceiling for 418MB of bidirectional streaming traffic (~93% of achievable).

#define NBATCH   32
#define NANCH    3
#define NCH      85                  // C+5
#define SPATIAL  6400                // 80*80
#define GW       80
#define TILE     64                  // spatial locations per block
#define NTILES   (SPATIAL / TILE)    // 100
#define THREADS  256
#define ELEMS    (TILE * NCH)        // 5440 floats
#define ELEMS4   (ELEMS / 4)         // 1360 float4
#define NBATCHJ  6                   // ceil(1360/256)
#define SCALE    409600.0f           // 640*640

__device__ __forceinline__ float fast_sigmoid(float x)
{
    float t;
    asm("tanh.approx.f32 %0, %1;" : "=f"(t) : "f"(0.5f * x));
    return fmaf(0.5f, t, 0.5f);
}

__global__ __launch_bounds__(THREADS)
void yolo_decode_kernel(const float* __restrict__ in, float* __restrict__ out)
{
    __shared__ __align__(128) float sm[ELEMS];   // 21.76 KB

    const int bt   = blockIdx.x;
    const int tile = bt % NTILES;
    const int na   = bt / NTILES;      // 0..95 = n*3 + a
    const int a    = na % NANCH;

    const float awS = ((a == 0) ? 10.0f : (a == 1) ? 16.0f : 33.0f) * SCALE;
    const float ahS = ((a == 0) ? 13.0f : (a == 1) ? 30.0f : 23.0f) * SCALE;

    const int s_base   = tile * TILE;
    // input elem (n, a*85+c, s): (na*85 + c)*6400 + s
    const int base_in  = (na * NCH) * SPATIAL + s_base;
    // output elem (n, a*6400+s, c): (na*6400 + s)*85 + c
    const int base_out = (na * SPATIAL + s_base) * NCH;

    const float4* __restrict__ in4 = reinterpret_cast<const float4*>(in);
    const int base4 = base_in >> 2;

    // ---- Phase 1a: front-batch 6 independent streaming LDG.128 per thread.
    float4 v[NBATCHJ];
    #pragma unroll
    for (int j = 0; j < NBATCHJ; j++) {
        const int q = threadIdx.x + j * THREADS;
        if (q < ELEMS4) {
            const int c  = q >> 4;
            const int sq = q & 15;
            v[j] = __ldcs(&in4[base4 + c * (SPATIAL / 4) + sq]);
        }
    }

    // ---- Phase 1b: transform + transposed STS (sm[s0*85 + c]).
    #pragma unroll
    for (int j = 0; j < NBATCHJ; j++) {
        const int q = threadIdx.x + j * THREADS;
        if (q < ELEMS4) {
            const int c  = q >> 4;
            const int s0 = (q & 15) << 2;
            const float vv[4] = { v[j].x, v[j].y, v[j].z, v[j].w };
            #pragma unroll
            for (int k = 0; k < 4; k++) {
                const float x = vv[k];
                float r;
                if (c >= 4) {
                    r = fast_sigmoid(x);
                } else if (c == 0) {
                    const int sabs = s_base + s0 + k;
                    r = (fast_sigmoid(x) + (float)(sabs % GW)) * SCALE;
                } else if (c == 1) {
                    const int sabs = s_base + s0 + k;
                    r = (fast_sigmoid(x) + (float)(sabs / GW)) * SCALE;
                } else if (c == 2) {
                    r = __expf(x) * awS;
                } else { // c == 3
                    r = __expf(x) * ahS;
                }
                sm[(s0 + k) * NCH + c] = r;
            }
        }
    }

    __syncthreads();

    // ---- Phase 2: contiguous float4 streaming stores (evict-first).
    const float4* __restrict__ sm4  = reinterpret_cast<const float4*>(sm);
    float4*       __restrict__ out4 = reinterpret_cast<float4*>(out + base_out);
    #pragma unroll
    for (int j = 0; j < NBATCHJ; j++) {
        const int q = threadIdx.x + j * THREADS;
        if (q < ELEMS4) __stcs(&out4[q], sm4[q]);
    }
}

extern "C" void kernel_launch(void* const* d_in, const int* in_sizes, int n_in,
                              void* d_out, int out_size)
{
    const float* x   = (const float*)d_in[0];
    float*       out = (float*)d_out;
    (void)in_sizes; (void)n_in; (void)out_size;

    const int grid = NBATCH * NANCH * NTILES;   // 9600
    yolo_decode_kernel<<<grid, THREADS>>>(x, out);
}